// round 16
// baseline (speedup 1.0000x reference)
#include <cuda_runtime.h>
#include <cuda_fp16.h>

// ---------------- problem constants ----------------
#define Bv 16
#define Cv 64
#define Nv 4096
#define Mv 1024
#define LN2R 1.4426950408889634f

typedef unsigned long long ULL;

// ---------------- helpers ----------------
__device__ __forceinline__ ULL f2_fma(ULL a, ULL b, ULL c) {
    ULL d; asm("fma.rn.f32x2 %0, %1, %2, %3;" : "=l"(d) : "l"(a), "l"(b), "l"(c)); return d;
}
__device__ __forceinline__ ULL f2_pack(float lo, float hi) {
    ULL r;
    asm("mov.b64 %0, {%1, %2};" : "=l"(r)
        : "r"(__float_as_uint(lo)), "r"(__float_as_uint(hi)));
    return r;
}
__device__ __forceinline__ float2 f2_unpack(ULL v) {
    unsigned lo, hi;
    asm("mov.b64 {%0, %1}, %2;" : "=r"(lo), "=r"(hi) : "l"(v));
    return make_float2(__uint_as_float(lo), __uint_as_float(hi));
}
// pack (hi, lo) f32 -> f16x2 (first source -> upper half)
__device__ __forceinline__ unsigned cvt_f16x2(float hi, float lo) {
    unsigned r;
    asm("cvt.rn.f16x2.f32 %0, %1, %2;" : "=r"(r) : "f"(hi), "f"(lo));
    return r;
}
__device__ __forceinline__ unsigned ex2_f16x2(unsigned v) {
    unsigned r; asm("ex2.approx.f16x2 %0, %1;" : "=r"(r) : "r"(v)); return r;
}
__device__ __forceinline__ unsigned smem_u32(const void* p) {
    unsigned a;
    asm("{.reg .u64 t; cvta.to.shared.u64 t, %1; cvt.u32.u64 %0, t;}"
        : "=r"(a) : "l"(p));
    return a;
}
__device__ __forceinline__ void cpa16(unsigned dst, const void* src) {
    asm volatile("cp.async.cg.shared.global [%0], [%1], 16;"
                 :: "r"(dst), "l"(src));
}
#define CPA_COMMIT() asm volatile("cp.async.commit_group;" ::: "memory")
#define CPA_WAIT0()  asm volatile("cp.async.wait_group 0;" ::: "memory")

#define LDSM4(r, a) \
    asm volatile("ldmatrix.sync.aligned.m8n8.x4.shared.b16 {%0,%1,%2,%3},[%4];" \
        : "=r"((r)[0]), "=r"((r)[1]), "=r"((r)[2]), "=r"((r)[3]) : "r"(a))

// mma.sync m16n8k8 f16: D = A(16x8) * B(8x8) + 0, f32 accum
__device__ __forceinline__ void mma_qk16(float d[4], const unsigned a[2],
                                         unsigned b0) {
    asm("mma.sync.aligned.m16n8k8.row.col.f32.f16.f16.f32 "
        "{%0,%1,%2,%3},{%4,%5},{%6},{%7,%8,%9,%10};"
        : "=f"(d[0]), "=f"(d[1]), "=f"(d[2]), "=f"(d[3])
        : "r"(a[0]), "r"(a[1]), "r"(b0),
          "f"(0.f), "f"(0.f), "f"(0.f), "f"(0.f));
}
// mma.sync m16n8k16 f16 (accumulate in place, f32 accum)
__device__ __forceinline__ void mma_pv(float d[4], const unsigned a[4],
                                       unsigned b0, unsigned b1) {
    asm("mma.sync.aligned.m16n8k16.row.col.f32.f16.f16.f32 "
        "{%0,%1,%2,%3},{%4,%5,%6,%7},{%8,%9},{%0,%1,%2,%3};"
        : "+f"(d[0]), "+f"(d[1]), "+f"(d[2]), "+f"(d[3])
        : "r"(a[0]), "r"(a[1]), "r"(a[2]), "r"(a[3]), "r"(b0), "r"(b1));
}

// ---------------- scratch ----------------
__device__ __half d_theta[Bv * Nv * 8];       // [b][n][k] f16, *LN2R
__device__ __half d_phi  [Bv * Mv * 8];       // [b][m][k]  f16 (natural order)
__device__ __half d_gTh  [Bv * 32 * Mv];      // [b][j][m]  f16

// ======================================================================
// prep_kernel (fused, single pass over x): grid (8, B), 256 threads.
// ======================================================================
__global__ void __launch_bounds__(256)
prep_kernel(const float* __restrict__ x,
            const float* __restrict__ Wth,
            const float* __restrict__ Wphi,
            const float* __restrict__ Wg) {
    __shared__ float Wt[64 * 48];        // [c][0:8)=theta [8:16)=phi [16:48)=g
    __shared__ float red[128 * 41];

    int tid = threadIdx.x;
    int b = blockIdx.y;

    for (int i = tid; i < 512; i += 256) {
        int k = i >> 6, c = i & 63;
        Wt[c * 48 + k] = Wth[i];
        Wt[c * 48 + 8 + k] = Wphi[i];
    }
    for (int i = tid; i < 2048; i += 256) {
        int j = i >> 6, c = i & 63;
        Wt[c * 48 + 16 + j] = Wg[i];
    }
    __syncthreads();

    int lm = tid & 127, half = tid >> 7;
    int m = blockIdx.x * 128 + lm;
    int h2 = m >> 5, w2 = m & 31;
    int n0 = ((h2 << 1) + half) * 64 + (w2 << 1);
    const float* xb = x + ((size_t)b * Cv) * Nv + n0;

    ULL acc0[24], acc1[24];
#pragma unroll
    for (int i = 0; i < 24; i++) { acc0[i] = 0ULL; acc1[i] = 0ULL; }

#pragma unroll 8
    for (int c = 0; c < 64; c++) {
        float2 xv = *(const float2*)(xb + (size_t)c * Nv);
        ULL xx0 = f2_pack(xv.x, xv.x);
        ULL xx1 = f2_pack(xv.y, xv.y);
        const ulonglong2* wr = (const ulonglong2*)&Wt[c * 48];
#pragma unroll
        for (int i = 0; i < 12; i++) {
            ulonglong2 wv = wr[i];
            acc0[2 * i]     = f2_fma(wv.x, xx0, acc0[2 * i]);
            acc0[2 * i + 1] = f2_fma(wv.y, xx0, acc0[2 * i + 1]);
            acc1[2 * i]     = f2_fma(wv.x, xx1, acc1[2 * i]);
            acc1[2 * i + 1] = f2_fma(wv.y, xx1, acc1[2 * i + 1]);
        }
    }

    // ---- theta (f16, *LN2R): both pixels ----
    {
        float t0[8], t1[8];
#pragma unroll
        for (int i = 0; i < 4; i++) {
            float2 v0 = f2_unpack(acc0[i]);
            float2 v1 = f2_unpack(acc1[i]);
            t0[2 * i] = v0.x * LN2R; t0[2 * i + 1] = v0.y * LN2R;
            t1[2 * i] = v1.x * LN2R; t1[2 * i + 1] = v1.y * LN2R;
        }
        ((uint4*)d_theta)[(size_t)(b * Nv + n0)] =
            make_uint4(cvt_f16x2(t0[1], t0[0]), cvt_f16x2(t0[3], t0[2]),
                       cvt_f16x2(t0[5], t0[4]), cvt_f16x2(t0[7], t0[6]));
        ((uint4*)d_theta)[(size_t)(b * Nv + n0 + 1)] =
            make_uint4(cvt_f16x2(t1[1], t1[0]), cvt_f16x2(t1[3], t1[2]),
                       cvt_f16x2(t1[5], t1[4]), cvt_f16x2(t1[7], t1[6]));
    }

    float bp[8], bg[32];
#pragma unroll
    for (int i = 0; i < 4; i++) {
        float2 v0 = f2_unpack(acc0[4 + i]);
        float2 v1 = f2_unpack(acc1[4 + i]);
        bp[2 * i] = fmaxf(v0.x, v1.x);
        bp[2 * i + 1] = fmaxf(v0.y, v1.y);
    }
#pragma unroll
    for (int i = 0; i < 16; i++) {
        float2 v0 = f2_unpack(acc0[8 + i]);
        float2 v1 = f2_unpack(acc1[8 + i]);
        bg[2 * i] = fmaxf(v0.x, v1.x);
        bg[2 * i + 1] = fmaxf(v0.y, v1.y);
    }

    if (half) {
        float* r = red + lm * 41;
#pragma unroll
        for (int k = 0; k < 8; k++) r[k] = bp[k];
#pragma unroll
        for (int j = 0; j < 32; j++) r[8 + j] = bg[j];
    }
    __syncthreads();
    if (!half) {
        const float* r = red + lm * 41;
#pragma unroll
        for (int k = 0; k < 8; k++) bp[k] = fmaxf(bp[k], r[k]);
#pragma unroll
        for (int j = 0; j < 32; j++) bg[j] = fmaxf(bg[j], r[8 + j]);

        // phi f16, natural k order
        ((uint4*)d_phi)[(size_t)(b * Mv + m)] =
            make_uint4(cvt_f16x2(bp[1], bp[0]), cvt_f16x2(bp[3], bp[2]),
                       cvt_f16x2(bp[5], bp[4]), cvt_f16x2(bp[7], bp[6]));
#pragma unroll
        for (int j = 0; j < 32; j++)
            d_gTh[((size_t)(b * 32 + j)) * Mv + m] = __float2half(bg[j]);
    }
}

// ======================================================================
// attn_kernel: in-CTA split-K. grid (32, B), 512 thr = 16 warps.
//   grp = w>>3 selects key half (512 keys = 4 tiles); wl = w&7 -> 16 q.
//   All 512 threads cooperatively double-buffer BOTH groups' tiles.
// smem (43008B): phi [2 buf][2 grp][2048B] at 0
//                gt  [2 buf][2 grp][8704B] at 8192
// epilogue overlay: o_s[2][128][32] at 0 | lsum[2][128] at 32768
//                   wa[2048] at 33792
// ======================================================================
#define ONES_F16X2 0x3C003C00u

__global__ void __launch_bounds__(512, 2)
attn_kernel(const float* __restrict__ x,
            const float* __restrict__ Wattn,
            const float* __restrict__ sigma,
            float* __restrict__ out) {
    __shared__ __align__(16) char smraw[43008];
    unsigned sbase = smem_u32(smraw);

    int tid = threadIdx.x;
    int w = tid >> 5, l = tid & 31;
    int g = l >> 2, k4 = l & 3;
    int grp = w >> 3, wl = w & 7;
    int b = blockIdx.y;
    int qbase = blockIdx.x * 128;

    // theta A-frag (f16): 16 queries
    unsigned a[2];
    {
        const __half* th = d_theta + ((size_t)(b * Nv + qbase + wl * 16)) * 8;
        a[0] = *(const unsigned*)(th + g * 8 + 2 * k4);
        a[1] = *(const unsigned*)(th + (g + 8) * 8 + 2 * k4);
    }

    float o[4][4];
#pragma unroll
    for (int jt = 0; jt < 4; jt++)
#pragma unroll
        for (int i = 0; i < 4; i++) o[jt][i] = 0.f;
    float oS[4] = {0.f, 0.f, 0.f, 0.f};

    const char* phi_g = (const char*)(d_phi + (size_t)b * (Mv * 8));
    const char* gt_g = (const char*)(d_gTh + (size_t)b * (32 * Mv));

    // ---- stage round 0 into buffer 0 (tiles grp0:0, grp1:4) ----
    {
        if (tid < 256) {
            int gp = tid >> 7, i = tid & 127;
            cpa16(sbase + gp * 2048 + i * 16,
                  phi_g + (size_t)(gp * 4) * 2048 + i * 16);
        }
#pragma unroll
        for (int r = 0; r < 2; r++) {
            int idx = tid + 512 * r;
            int gp = idx >> 9, within = idx & 511;
            int row = within >> 4, c = within & 15;
            cpa16(sbase + 8192 + gp * 8704 + row * 272 + c * 16,
                  gt_g + (size_t)row * (Mv * 2) + (gp * 4) * 256 + c * 16);
        }
        CPA_COMMIT();
    }

#pragma unroll 1
    for (int t = 0; t < 4; t++) {
        CPA_WAIT0();
        __syncthreads();

        int buf = t & 1;
        if (t < 3) {
            int nb = buf ^ 1;
            if (tid < 256) {
                int gp = tid >> 7, i = tid & 127;
                cpa16(sbase + nb * 4096 + gp * 2048 + i * 16,
                      phi_g + (size_t)(gp * 4 + t + 1) * 2048 + i * 16);
            }
#pragma unroll
            for (int r = 0; r < 2; r++) {
                int idx = tid + 512 * r;
                int gp = idx >> 9, within = idx & 511;
                int row = within >> 4, c = within & 15;
                cpa16(sbase + 8192 + nb * 17408 + gp * 8704 + row * 272 + c * 16,
                      gt_g + (size_t)row * (Mv * 2) + (gp * 4 + t + 1) * 256 + c * 16);
            }
            CPA_COMMIT();
        }

        const char* phi_b = smraw + buf * 4096 + grp * 2048;
        unsigned gt_lane = sbase + 8192 + buf * 17408 + grp * 8704
                           + (unsigned)l * 272;

#pragma unroll
        for (int ms = 0; ms < 8; ms++) {
            unsigned bg0[4], bg1[4];
            LDSM4(bg0, gt_lane + ms * 32);
            LDSM4(bg1, gt_lane + ms * 32 + 16);

            // phi B-frags (f16, k8): lane n = g, k-pair = 2*k4
            unsigned pb0 = *(const unsigned*)(phi_b + (ms * 16 + g) * 16 + k4 * 4);
            unsigned pb1 = *(const unsigned*)(phi_b + (ms * 16 + 8 + g) * 16 + k4 * 4);

            float s0[4], s1[4];
            mma_qk16(s0, a, pb0);
            mma_qk16(s1, a, pb1);

            unsigned pa[4];
            pa[0] = ex2_f16x2(cvt_f16x2(s0[1], s0[0]));
            pa[1] = ex2_f16x2(cvt_f16x2(s0[3], s0[2]));
            pa[2] = ex2_f16x2(cvt_f16x2(s1[1], s1[0]));
            pa[3] = ex2_f16x2(cvt_f16x2(s1[3], s1[2]));

#pragma unroll
            for (int jt = 0; jt < 4; jt++)
                mma_pv(o[jt], pa, bg0[jt], bg1[jt]);
            mma_pv(oS, pa, ONES_F16X2, ONES_F16X2);
        }
    }

    __syncthreads();   // all compute done; overlay epilogue arrays
    float* o_s = (float*)smraw;                 // [2][128][32]
    float* lsum_s = (float*)(smraw + 32768);    // [2][128]
    float* wa_s = (float*)(smraw + 33792);      // [2048]

    {
        float* og = o_s + grp * 4096;
        int q0 = wl * 16;
#pragma unroll
        for (int jt = 0; jt < 4; jt++) {
            int jc = jt * 8 + 2 * k4;
            *(float2*)&og[(q0 + g) * 32 + jc] = make_float2(o[jt][0], o[jt][1]);
            *(float2*)&og[(q0 + g + 8) * 32 + jc] = make_float2(o[jt][2], o[jt][3]);
        }
        if (k4 == 0) {
            lsum_s[grp * 128 + q0 + g] = oS[0];
            lsum_s[grp * 128 + q0 + g + 8] = oS[2];
        }
    }
    for (int i = tid; i < 2048; i += 512) wa_s[i] = Wattn[i];
    __syncthreads();

    // epilogue: 4 threads per query, 16 output channels each
    int q = tid & 127;
    int part = tid >> 7;
    float inv = sigma[0] / (lsum_s[q] + lsum_s[128 + q]);

    ULL acc[16];
    {
        const float4* os0 = (const float4*)(o_s + q * 32);
        const float4* os1 = (const float4*)(o_s + 4096 + q * 32);
#pragma unroll
        for (int i = 0; i < 8; i++) {
            float4 v = os0[i];
            float4 p = os1[i];
            acc[2 * i]     = f2_pack((v.x + p.x) * inv, (v.y + p.y) * inv);
            acc[2 * i + 1] = f2_pack((v.z + p.z) * inv, (v.w + p.w) * inv);
        }
    }

    int n = qbase + q;
    int co0 = part * 16;
    const float* xp = x + ((size_t)b * Cv + co0) * Nv + n;
    float* op = out + ((size_t)b * Cv + co0) * Nv + n;
    const ulonglong2* wa_u = (const ulonglong2*)wa_s;
#pragma unroll 4
    for (int c = 0; c < 16; c++) {
        const ulonglong2* wr = wa_u + (size_t)(co0 + c) * 8;
        ULL d2 = 0ULL;
#pragma unroll
        for (int jj = 0; jj < 8; jj++) {
            ulonglong2 wv = wr[jj];
            d2 = f2_fma(acc[jj * 2 + 0], wv.x, d2);
            d2 = f2_fma(acc[jj * 2 + 1], wv.y, d2);
        }
        float2 df = f2_unpack(d2);
        op[(size_t)c * Nv] = xp[(size_t)c * Nv] + (df.x + df.y);
    }
}

// ======================================================================
// launch
// ======================================================================
extern "C" void kernel_launch(void* const* d_in, const int* in_sizes, int n_in,
                              void* d_out, int out_size) {
    const float* x     = (const float*)d_in[0];
    const float* Wth   = (const float*)d_in[1];
    const float* Wphi  = (const float*)d_in[2];
    const float* Wg    = (const float*)d_in[3];
    const float* Wattn = (const float*)d_in[4];
    const float* sigma = (const float*)d_in[5];
    float* out = (float*)d_out;

    prep_kernel<<<dim3(8, Bv), 256>>>(x, Wth, Wphi, Wg);
    attn_kernel<<<dim3(Nv / 128, Bv), 512>>>(x, Wattn, sigma, out);
}

// round 17
// speedup vs baseline: 1.2711x; 1.2711x over previous
#include <cuda_runtime.h>
#include <cuda_fp16.h>

// ---------------- problem constants ----------------
#define Bv 16
#define Cv 64
#define Nv 4096
#define Mv 1024
#define LN2R 1.4426950408889634f

typedef unsigned long long ULL;

// ---------------- helpers ----------------
__device__ __forceinline__ ULL f2_fma(ULL a, ULL b, ULL c) {
    ULL d; asm("fma.rn.f32x2 %0, %1, %2, %3;" : "=l"(d) : "l"(a), "l"(b), "l"(c)); return d;
}
__device__ __forceinline__ ULL f2_pack(float lo, float hi) {
    ULL r;
    asm("mov.b64 %0, {%1, %2};" : "=l"(r)
        : "r"(__float_as_uint(lo)), "r"(__float_as_uint(hi)));
    return r;
}
__device__ __forceinline__ float2 f2_unpack(ULL v) {
    unsigned lo, hi;
    asm("mov.b64 {%0, %1}, %2;" : "=r"(lo), "=r"(hi) : "l"(v));
    return make_float2(__uint_as_float(lo), __uint_as_float(hi));
}
// pack (hi, lo) f32 -> f16x2 (first source -> upper half)
__device__ __forceinline__ unsigned cvt_f16x2(float hi, float lo) {
    unsigned r;
    asm("cvt.rn.f16x2.f32 %0, %1, %2;" : "=r"(r) : "f"(hi), "f"(lo));
    return r;
}
__device__ __forceinline__ unsigned ex2_f16x2(unsigned v) {
    unsigned r; asm("ex2.approx.f16x2 %0, %1;" : "=r"(r) : "r"(v)); return r;
}
__device__ __forceinline__ unsigned smem_u32(const void* p) {
    unsigned a;
    asm("{.reg .u64 t; cvta.to.shared.u64 t, %1; cvt.u32.u64 %0, t;}"
        : "=r"(a) : "l"(p));
    return a;
}
__device__ __forceinline__ void cpa16(unsigned dst, const void* src) {
    asm volatile("cp.async.cg.shared.global [%0], [%1], 16;"
                 :: "r"(dst), "l"(src));
}
#define CPA_COMMIT() asm volatile("cp.async.commit_group;" ::: "memory")
#define CPA_WAIT0()  asm volatile("cp.async.wait_group 0;" ::: "memory")

#define LDSM4(r, a) \
    asm volatile("ldmatrix.sync.aligned.m8n8.x4.shared.b16 {%0,%1,%2,%3},[%4];" \
        : "=r"((r)[0]), "=r"((r)[1]), "=r"((r)[2]), "=r"((r)[3]) : "r"(a))

// mma.sync m16n8k8 f16: D = A(16x8) * B(8x8) + 0, f32 accum
__device__ __forceinline__ void mma_qk16(float d[4], const unsigned a[2],
                                         unsigned b0) {
    asm("mma.sync.aligned.m16n8k8.row.col.f32.f16.f16.f32 "
        "{%0,%1,%2,%3},{%4,%5},{%6},{%7,%8,%9,%10};"
        : "=f"(d[0]), "=f"(d[1]), "=f"(d[2]), "=f"(d[3])
        : "r"(a[0]), "r"(a[1]), "r"(b0),
          "f"(0.f), "f"(0.f), "f"(0.f), "f"(0.f));
}
// mma.sync m16n8k16 f16 (accumulate in place, f32 accum)
__device__ __forceinline__ void mma_pv(float d[4], const unsigned a[4],
                                       unsigned b0, unsigned b1) {
    asm("mma.sync.aligned.m16n8k16.row.col.f32.f16.f16.f32 "
        "{%0,%1,%2,%3},{%4,%5,%6,%7},{%8,%9},{%0,%1,%2,%3};"
        : "+f"(d[0]), "+f"(d[1]), "+f"(d[2]), "+f"(d[3])
        : "r"(a[0]), "r"(a[1]), "r"(a[2]), "r"(a[3]), "r"(b0), "r"(b1));
}

// ---------------- scratch ----------------
__device__ __half d_theta[Bv * Nv * 8];       // [b][n][k] f16, *LN2R
__device__ __half d_phi  [Bv * Mv * 8];       // [b][m][k]  f16 (natural order)
__device__ __half d_gTh  [Bv * 32 * Mv];      // [b][j][m]  f16

// ======================================================================
// prep_kernel (fused, single pass over x): grid (8, B), 256 threads.
// ======================================================================
__global__ void __launch_bounds__(256)
prep_kernel(const float* __restrict__ x,
            const float* __restrict__ Wth,
            const float* __restrict__ Wphi,
            const float* __restrict__ Wg) {
    __shared__ float Wt[64 * 48];        // [c][0:8)=theta [8:16)=phi [16:48)=g
    __shared__ float red[128 * 41];

    int tid = threadIdx.x;
    int b = blockIdx.y;

    for (int i = tid; i < 512; i += 256) {
        int k = i >> 6, c = i & 63;
        Wt[c * 48 + k] = Wth[i];
        Wt[c * 48 + 8 + k] = Wphi[i];
    }
    for (int i = tid; i < 2048; i += 256) {
        int j = i >> 6, c = i & 63;
        Wt[c * 48 + 16 + j] = Wg[i];
    }
    __syncthreads();

    int lm = tid & 127, half = tid >> 7;
    int m = blockIdx.x * 128 + lm;
    int h2 = m >> 5, w2 = m & 31;
    int n0 = ((h2 << 1) + half) * 64 + (w2 << 1);
    const float* xb = x + ((size_t)b * Cv) * Nv + n0;

    ULL acc0[24], acc1[24];
#pragma unroll
    for (int i = 0; i < 24; i++) { acc0[i] = 0ULL; acc1[i] = 0ULL; }

#pragma unroll 8
    for (int c = 0; c < 64; c++) {
        float2 xv = *(const float2*)(xb + (size_t)c * Nv);
        ULL xx0 = f2_pack(xv.x, xv.x);
        ULL xx1 = f2_pack(xv.y, xv.y);
        const ulonglong2* wr = (const ulonglong2*)&Wt[c * 48];
#pragma unroll
        for (int i = 0; i < 12; i++) {
            ulonglong2 wv = wr[i];
            acc0[2 * i]     = f2_fma(wv.x, xx0, acc0[2 * i]);
            acc0[2 * i + 1] = f2_fma(wv.y, xx0, acc0[2 * i + 1]);
            acc1[2 * i]     = f2_fma(wv.x, xx1, acc1[2 * i]);
            acc1[2 * i + 1] = f2_fma(wv.y, xx1, acc1[2 * i + 1]);
        }
    }

    // ---- theta (f16, *LN2R): both pixels ----
    {
        float t0[8], t1[8];
#pragma unroll
        for (int i = 0; i < 4; i++) {
            float2 v0 = f2_unpack(acc0[i]);
            float2 v1 = f2_unpack(acc1[i]);
            t0[2 * i] = v0.x * LN2R; t0[2 * i + 1] = v0.y * LN2R;
            t1[2 * i] = v1.x * LN2R; t1[2 * i + 1] = v1.y * LN2R;
        }
        ((uint4*)d_theta)[(size_t)(b * Nv + n0)] =
            make_uint4(cvt_f16x2(t0[1], t0[0]), cvt_f16x2(t0[3], t0[2]),
                       cvt_f16x2(t0[5], t0[4]), cvt_f16x2(t0[7], t0[6]));
        ((uint4*)d_theta)[(size_t)(b * Nv + n0 + 1)] =
            make_uint4(cvt_f16x2(t1[1], t1[0]), cvt_f16x2(t1[3], t1[2]),
                       cvt_f16x2(t1[5], t1[4]), cvt_f16x2(t1[7], t1[6]));
    }

    float bp[8], bg[32];
#pragma unroll
    for (int i = 0; i < 4; i++) {
        float2 v0 = f2_unpack(acc0[4 + i]);
        float2 v1 = f2_unpack(acc1[4 + i]);
        bp[2 * i] = fmaxf(v0.x, v1.x);
        bp[2 * i + 1] = fmaxf(v0.y, v1.y);
    }
#pragma unroll
    for (int i = 0; i < 16; i++) {
        float2 v0 = f2_unpack(acc0[8 + i]);
        float2 v1 = f2_unpack(acc1[8 + i]);
        bg[2 * i] = fmaxf(v0.x, v1.x);
        bg[2 * i + 1] = fmaxf(v0.y, v1.y);
    }

    if (half) {
        float* r = red + lm * 41;
#pragma unroll
        for (int k = 0; k < 8; k++) r[k] = bp[k];
#pragma unroll
        for (int j = 0; j < 32; j++) r[8 + j] = bg[j];
    }
    __syncthreads();
    if (!half) {
        const float* r = red + lm * 41;
#pragma unroll
        for (int k = 0; k < 8; k++) bp[k] = fmaxf(bp[k], r[k]);
#pragma unroll
        for (int j = 0; j < 32; j++) bg[j] = fmaxf(bg[j], r[8 + j]);

        ((uint4*)d_phi)[(size_t)(b * Mv + m)] =
            make_uint4(cvt_f16x2(bp[1], bp[0]), cvt_f16x2(bp[3], bp[2]),
                       cvt_f16x2(bp[5], bp[4]), cvt_f16x2(bp[7], bp[6]));
#pragma unroll
        for (int j = 0; j < 32; j++)
            d_gTh[((size_t)(b * 32 + j)) * Mv + m] = __float2half(bg[j]);
    }
}

// ======================================================================
// attn_kernel: within-tile k-split. grid (64, B) = 1024 CTAs.
// 128 thr = 4 warps: qw = w&1 (2 q-warps x 32q = 64 q/CTA),
//                    grp = w>>1 (steps 0-3 vs 4-7 of each staged tile).
// All warps share the SAME staged tiles -> L1 traffic identical to R10,
// but 2x the warps (4096) and 5 CTAs/SM target.
// smem (21504B): phi dbuf 2x2048 at 0 | gt dbuf 2x8704 at 4096
// epilogue overlay: o_s[64][32] at 0 (8KB) | lsum[64] at 8192 | wa at 8448
// ======================================================================
#define ONES_F16X2 0x3C003C00u

__global__ void __launch_bounds__(128, 5)
attn_kernel(const float* __restrict__ x,
            const float* __restrict__ Wattn,
            const float* __restrict__ sigma,
            float* __restrict__ out) {
    __shared__ __align__(16) char smraw[21504];
    unsigned sbase = smem_u32(smraw);

    int tid = threadIdx.x;
    int w = tid >> 5, l = tid & 31;
    int g = l >> 2, k4 = l & 3;
    int qw = w & 1, grp = w >> 1;
    int b = blockIdx.y;
    int qbase = blockIdx.x * 64;

    // two f16 A-frags: queries qbase + qw*32 + [0,16) and [16,32)
    unsigned aA[2], aB[2];
    {
        const __half* th = d_theta + ((size_t)(b * Nv + qbase + qw * 32)) * 8;
        aA[0] = *(const unsigned*)(th + g * 8 + 2 * k4);
        aA[1] = *(const unsigned*)(th + (g + 8) * 8 + 2 * k4);
        const __half* tb = th + 128;
        aB[0] = *(const unsigned*)(tb + g * 8 + 2 * k4);
        aB[1] = *(const unsigned*)(tb + (g + 8) * 8 + 2 * k4);
    }

    float oA[4][4], oB[4][4];
#pragma unroll
    for (int jt = 0; jt < 4; jt++)
#pragma unroll
        for (int i = 0; i < 4; i++) { oA[jt][i] = 0.f; oB[jt][i] = 0.f; }
    float oSA[4] = {0.f, 0.f, 0.f, 0.f};
    float oSB[4] = {0.f, 0.f, 0.f, 0.f};

    const char* phi_g = (const char*)(d_phi + (size_t)b * (Mv * 8));
    const char* gt_g = (const char*)(d_gTh + (size_t)b * (32 * Mv));

    // ---- stage tile 0 into buffer 0 (128 thr: 1 phi + 4 gt cpa16 each) ----
    {
        cpa16(sbase + tid * 16, phi_g + tid * 16);
#pragma unroll
        for (int r = 0; r < 4; r++) {
            int idx = tid + 128 * r;
            int row = idx >> 4, c = idx & 15;
            cpa16(sbase + 4096 + row * 272 + c * 16,
                  gt_g + (size_t)row * (Mv * 2) + c * 16);
        }
        CPA_COMMIT();
    }

#pragma unroll 1
    for (int t = 0; t < 8; t++) {
        CPA_WAIT0();
        __syncthreads();

        int buf = t & 1;
        if (t < 7) {
            int nb = buf ^ 1;
            const char* psrc = phi_g + (size_t)(t + 1) * 2048;
            const char* gsrc = gt_g + (size_t)(t + 1) * 256;
            cpa16(sbase + nb * 2048 + tid * 16, psrc + tid * 16);
#pragma unroll
            for (int r = 0; r < 4; r++) {
                int idx = tid + 128 * r;
                int row = idx >> 4, c = idx & 15;
                cpa16(sbase + 4096 + nb * 8704 + row * 272 + c * 16,
                      gsrc + (size_t)row * (Mv * 2) + c * 16);
            }
            CPA_COMMIT();
        }

        const char* phi_b = smraw + buf * 2048;
        unsigned gt_lane = sbase + 4096 + buf * 8704 + (unsigned)l * 272;

        // this group's 4 steps of the shared tile
#pragma unroll
        for (int ms2 = 0; ms2 < 4; ms2++) {
            int ms = grp * 4 + ms2;
            unsigned bg0[4], bg1[4];
            LDSM4(bg0, gt_lane + ms * 32);
            LDSM4(bg1, gt_lane + ms * 32 + 16);

            unsigned pb0 = *(const unsigned*)(phi_b + (ms * 16 + g) * 16 + k4 * 4);
            unsigned pb1 = *(const unsigned*)(phi_b + (ms * 16 + 8 + g) * 16 + k4 * 4);

            float sA0[4], sA1[4], sB0[4], sB1[4];
            mma_qk16(sA0, aA, pb0);
            mma_qk16(sA1, aA, pb1);
            mma_qk16(sB0, aB, pb0);
            mma_qk16(sB1, aB, pb1);

            unsigned paA[4], paB[4];
            paA[0] = ex2_f16x2(cvt_f16x2(sA0[1], sA0[0]));
            paA[1] = ex2_f16x2(cvt_f16x2(sA0[3], sA0[2]));
            paA[2] = ex2_f16x2(cvt_f16x2(sA1[1], sA1[0]));
            paA[3] = ex2_f16x2(cvt_f16x2(sA1[3], sA1[2]));
            paB[0] = ex2_f16x2(cvt_f16x2(sB0[1], sB0[0]));
            paB[1] = ex2_f16x2(cvt_f16x2(sB0[3], sB0[2]));
            paB[2] = ex2_f16x2(cvt_f16x2(sB1[1], sB1[0]));
            paB[3] = ex2_f16x2(cvt_f16x2(sB1[3], sB1[2]));

#pragma unroll
            for (int jt = 0; jt < 4; jt++) {
                mma_pv(oA[jt], paA, bg0[jt], bg1[jt]);
                mma_pv(oB[jt], paB, bg0[jt], bg1[jt]);
            }
            mma_pv(oSA, paA, ONES_F16X2, ONES_F16X2);
            mma_pv(oSB, paB, ONES_F16X2, ONES_F16X2);
        }
    }

    // ---- in-CTA combine of the two key-groups via smem ----
    __syncthreads();   // all compute done; overlay epilogue arrays
    float* o_s = (float*)smraw;                 // [64][32]
    float* lsum_s = (float*)(smraw + 8192);     // [64]
    float* wa_s = (float*)(smraw + 8448);       // [2048]

    if (grp == 1) {
        int q0 = qw * 32;
#pragma unroll
        for (int jt = 0; jt < 4; jt++) {
            int jc = jt * 8 + 2 * k4;
            *(float2*)&o_s[(q0 + g) * 32 + jc] = make_float2(oA[jt][0], oA[jt][1]);
            *(float2*)&o_s[(q0 + g + 8) * 32 + jc] = make_float2(oA[jt][2], oA[jt][3]);
            *(float2*)&o_s[(q0 + 16 + g) * 32 + jc] = make_float2(oB[jt][0], oB[jt][1]);
            *(float2*)&o_s[(q0 + 24 + g) * 32 + jc] = make_float2(oB[jt][2], oB[jt][3]);
        }
        if (k4 == 0) {
            lsum_s[q0 + g] = oSA[0];
            lsum_s[q0 + g + 8] = oSA[2];
            lsum_s[q0 + 16 + g] = oSB[0];
            lsum_s[q0 + 24 + g] = oSB[2];
        }
    }
    for (int i = tid; i < 2048; i += 128) wa_s[i] = Wattn[i];
    __syncthreads();

    if (grp == 0) {
        int q0 = qw * 32;
#pragma unroll
        for (int jt = 0; jt < 4; jt++) {
            int jc = jt * 8 + 2 * k4;
            float2 pA0 = *(float2*)&o_s[(q0 + g) * 32 + jc];
            float2 pA1 = *(float2*)&o_s[(q0 + g + 8) * 32 + jc];
            float2 pB0 = *(float2*)&o_s[(q0 + 16 + g) * 32 + jc];
            float2 pB1 = *(float2*)&o_s[(q0 + 24 + g) * 32 + jc];
            *(float2*)&o_s[(q0 + g) * 32 + jc] =
                make_float2(oA[jt][0] + pA0.x, oA[jt][1] + pA0.y);
            *(float2*)&o_s[(q0 + g + 8) * 32 + jc] =
                make_float2(oA[jt][2] + pA1.x, oA[jt][3] + pA1.y);
            *(float2*)&o_s[(q0 + 16 + g) * 32 + jc] =
                make_float2(oB[jt][0] + pB0.x, oB[jt][1] + pB0.y);
            *(float2*)&o_s[(q0 + 24 + g) * 32 + jc] =
                make_float2(oB[jt][2] + pB1.x, oB[jt][3] + pB1.y);
        }
        if (k4 == 0) {
            lsum_s[q0 + g] += oSA[0];
            lsum_s[q0 + g + 8] += oSA[2];
            lsum_s[q0 + 16 + g] += oSB[0];
            lsum_s[q0 + 24 + g] += oSB[2];
        }
    }
    __syncthreads();

    // epilogue: 2 threads per query, 32 output channels each
    int q = tid & 63;
    int part = tid >> 6;
    float inv = sigma[0] / lsum_s[q];

    ULL acc[16];
    {
        const float4* os = (const float4*)(o_s + q * 32);
#pragma unroll
        for (int i = 0; i < 8; i++) {
            float4 v = os[i];
            acc[2 * i]     = f2_pack(v.x * inv, v.y * inv);
            acc[2 * i + 1] = f2_pack(v.z * inv, v.w * inv);
        }
    }

    int n = qbase + q;
    int co0 = part * 32;
    const float* xp = x + ((size_t)b * Cv + co0) * Nv + n;
    float* op = out + ((size_t)b * Cv + co0) * Nv + n;
    const ulonglong2* wa_u = (const ulonglong2*)wa_s;
#pragma unroll 4
    for (int c = 0; c < 32; c++) {
        const ulonglong2* wr = wa_u + (size_t)(co0 + c) * 8;
        ULL d2 = 0ULL;
#pragma unroll
        for (int jj = 0; jj < 8; jj++) {
            ulonglong2 wv = wr[jj];
            d2 = f2_fma(acc[jj * 2 + 0], wv.x, d2);
            d2 = f2_fma(acc[jj * 2 + 1], wv.y, d2);
        }
        float2 df = f2_unpack(d2);
        op[(size_t)c * Nv] = xp[(size_t)c * Nv] + (df.x + df.y);
    }
}

// ======================================================================
// launch
// ======================================================================
extern "C" void kernel_launch(void* const* d_in, const int* in_sizes, int n_in,
                              void* d_out, int out_size) {
    const float* x     = (const float*)d_in[0];
    const float* Wth   = (const float*)d_in[1];
    const float* Wphi  = (const float*)d_in[2];
    const float* Wg    = (const float*)d_in[3];
    const float* Wattn = (const float*)d_in[4];
    const float* sigma = (const float*)d_in[5];
    float* out = (float*)d_out;

    prep_kernel<<<dim3(8, Bv), 256>>>(x, Wth, Wphi, Wg);
    attn_kernel<<<dim3(Nv / 64, Bv), 128>>>(x, Wattn, sigma, out);
}